// round 10
// baseline (speedup 1.0000x reference)
#include <cuda_runtime.h>

#define BS  2
#define TT  12
#define B   24
#define N   150
#define DIN 64
#define F   128
#define NN  (N*N)     // 22500

#define RT   15       // output rows per GEMM tile
#define RTP  20       // k1 STs row stride
#define WRP  16       // k2a Ws row stride
#define PTS2 152      // k2a PtS row stride
#define NT   320
#define WFS2 84
#define GEMB 480      // k1 GEMM blocks
#define ABLK 100
#define GBLK 24
#define K1G  (GEMB + ABLK + GBLK)   // 604

// ---------------- scratch ----------------
__device__ float d_Ptmp[B*NN];
__device__ float d_part0[B*NN];
__device__ float d_part1[B*NN];
__device__ float d_A0[BS*NN];
__device__ float d_A1[BS*NN];
__device__ float d_g[B*N];
__device__ float d_cnt0[BS*N];
__device__ float d_cnt1[BS*N];
__device__ float d_u0[BS*N];
__device__ float d_u1[BS*N];

// ==== K1: Ptmp GEMM | A0/A1+counts+colsums | g ====
__global__ __launch_bounds__(NT) void k1(
        const float* __restrict__ H, const float* __restrict__ E,
        const float* __restrict__ adj,
        const float* __restrict__ WBw, const float* __restrict__ WBb,
        const float* __restrict__ Wfu, const float* __restrict__ aw) {
    __shared__ __align__(16) float sm[5248];   // 21 KB union
    int bid = blockIdx.x, tid = threadIdx.x;

    if (bid < GEMB) {
        // ---- Ptmp GEMM: 15 rows x 80/70 cols, f-split x2 in-block ----
        float* STs = sm;             // 128*20 = 2560
        float* WfS = sm + 2560;      // 2*16*84 = 2688
        int tile2 = bid % 20, bt = bid / 20;
        int tile = tile2 >> 1, jh = tile2 & 1;
        int i0 = tile*RT;
        int W  = jh ? 70 : 80;

        for (int idx = tid; idx < RT*F; idx += NT) {
            int r = idx >> 7, f = idx & 127;
            int row = bt*N + i0 + r;
            float v = (f < DIN) ? H[row*DIN + f] : E[row*DIN + f - DIN];
            STs[f*RTP + r] = v;
        }
        if (tid < F) STs[tid*RTP + 15] = 0.f;
        __syncthreads();

        int kh = tid / 160, t = tid % 160;
        int rg = t / 40, j = t % 40;
        int barid = kh + 1;
        bool act = (j*2 < W);
        float* Wg = WfS + kh*(16*WFS2);

        float acc[4][2] = {};
        for (int fc = 0; fc < 4; fc++) {
            int f0 = kh*64 + fc*16;
            asm volatile("bar.sync %0, %1;" :: "r"(barid), "r"(160) : "memory");
            for (int idx = t; idx < 320; idx += 160) {
                int cc = idx >> 2, q = idx & 3;
                if (cc < W) {
                    float4 w4 = *(const float4*)(Wfu + (jh*80+cc)*F + f0 + q*4);
                    Wg[(q*4+0)*WFS2 + cc] = w4.x;
                    Wg[(q*4+1)*WFS2 + cc] = w4.y;
                    Wg[(q*4+2)*WFS2 + cc] = w4.z;
                    Wg[(q*4+3)*WFS2 + cc] = w4.w;
                }
            }
            asm volatile("bar.sync %0, %1;" :: "r"(barid), "r"(160) : "memory");
            if (act) {
                #pragma unroll
                for (int ff = 0; ff < 16; ff++) {
                    float4 s = *(const float4*)(STs + (f0+ff)*RTP + rg*4);
                    float2 w = *(const float2*)(Wg + ff*WFS2 + 2*j);
                    acc[0][0] += s.x*w.x; acc[0][1] += s.x*w.y;
                    acc[1][0] += s.y*w.x; acc[1][1] += s.y*w.y;
                    acc[2][0] += s.z*w.x; acc[2][1] += s.z*w.y;
                    acc[3][0] += s.w*w.x; acc[3][1] += s.w*w.y;
                }
            }
        }
        __syncthreads();
        float* red = WfS;
        if (kh == 1 && act) {
            #pragma unroll
            for (int u = 0; u < 4; u++) {
                int r = rg*4 + u;
                if (r < RT) {
                    red[r*80 + 2*j]   = acc[u][0];
                    red[r*80 + 2*j+1] = acc[u][1];
                }
            }
        }
        __syncthreads();
        if (kh == 0 && act) {
            #pragma unroll
            for (int u = 0; u < 4; u++) {
                int r = rg*4 + u;
                if (r < RT) {
                    float2 o = make_float2(acc[u][0] + red[r*80 + 2*j],
                                           acc[u][1] + red[r*80 + 2*j+1]);
                    *(float2*)(d_Ptmp + bt*NN + (i0+r)*N + jh*80 + 2*j) = o;
                }
            }
        }
        return;
    }

    if (bid < GEMB + ABLK) {
        // ---- A-half blocks ----
        float* adjS = sm;            // 900
        float* colS = sm + 900;      // 3750
        int ab = bid - GEMB;
        int tile = ab % 25, half = (ab / 25) & 1, b = ab / 50;
        const float* a = adj + b*NN;
        int i0 = tile*6, j0 = half*75;

        for (int idx = tid; idx < 6*N; idx += NT) adjS[idx] = a[i0*N + idx];
        __syncthreads();

        if (tid < 6) {
            float c = 0.f;
            #pragma unroll 5
            for (int j = 0; j < 75; j++)
                c += (adjS[tid*N + j0 + j] > 0.f) ? 1.f : 0.f;
            (half ? d_cnt1 : d_cnt0)[b*N + i0 + tid] = c;
        }

        int g2 = tid / 160, n = tid % 160;
        int r0 = g2*3;
        float a0 = 0.f, a1 = 0.f, a2 = 0.f, us = 0.f;
        for (int c = 0; c < 3; c++) {
            __syncthreads();
            const float* src = a + (j0 + c*25)*N;
            for (int idx = tid; idx < 25*N; idx += NT) colS[idx] = src[idx];
            __syncthreads();
            if (n < N) {
                int jb = j0 + c*25;
                #pragma unroll 5
                for (int jj = 0; jj < 25; jj++) {
                    float v = colS[jj*N + n];
                    us += v;
                    a0 += adjS[(r0+0)*N + jb + jj] * v;
                    a1 += adjS[(r0+1)*N + jb + jj] * v;
                    a2 += adjS[(r0+2)*N + jb + jj] * v;
                }
            }
        }
        if (n < N) {
            float* A = half ? d_A1 : d_A0;
            A[b*NN + (i0+r0+0)*N + n] = a0;
            A[b*NN + (i0+r0+1)*N + n] = a1;
            A[b*NN + (i0+r0+2)*N + n] = a2;
            if (g2 == 0 && tile == 0) (half ? d_u1 : d_u0)[b*N + n] = us;
        }
        return;
    }

    // ---- g-blocks: one per bt; wg derived locally, g = ST.wg + cg ----
    {
        float* wgS = sm;             // 129
        int bt = bid - GEMB - ABLK;
        if (tid < F) {
            float acc = 0.f;
            #pragma unroll 8
            for (int h = 0; h < 64; h++)
                acc += WBw[h*F + tid] * (aw[h] + aw[h+64]);
            wgS[tid] = acc;
        } else if (tid == F) {
            float acc = 0.f;
            for (int h = 0; h < 64; h++) acc += WBb[h] * (aw[h] + aw[h+64]);
            wgS[F] = acc;
        }
        __syncthreads();
        int n = tid >> 1, fh = tid & 1;
        int nc = n < N ? n : N-1;
        const float* src = fh ? E + (bt*N+nc)*DIN : H + (bt*N+nc)*DIN;
        float s = 0.f;
        #pragma unroll 8
        for (int u = 0; u < 64; u++) s += src[u] * wgS[fh*64 + u];
        s += __shfl_down_sync(0xffffffffu, s, 1);
        if (fh == 0 && n < N) d_g[bt*N + n] = s + wgS[F];
    }
}

// ==== K2a: partial = W_khalf @ Ptmp_khalf  (split-K x2 across blocks) ====
__global__ __launch_bounds__(NT) void k2a(float* __restrict__ dummy) {
    __shared__ __align__(16) float Ws[75*WRP];    // 4.8 KB
    __shared__ __align__(16) float PtS[25*PTS2];  // 15.2 KB
    __shared__ float p0s[RT], p1s[RT];
    __shared__ int   flm[RT];
    int tile = blockIdx.x, bt = blockIdx.y, kh = blockIdx.z;
    int b = bt / TT;
    int tid = threadIdx.x;
    int i0 = tile*RT;
    int kbase = kh*75;

    if (tid < RT) {
        int i = i0 + tid;
        float v0 = d_g[bt*N + (2*i)   % N];
        float v1 = d_g[bt*N + (2*i+1) % N];
        float l0 = v0 > 0.f ? v0 : 0.2f*v0;
        float l1 = v1 > 0.f ? v1 : 0.2f*v1;
        float c0 = d_cnt0[b*N + i], c1 = d_cnt1[b*N + i];
        if (c0 + c1 > 0.f) {
            float mx = fmaxf(l0, l1);
            float e0 = expf(l0 - mx), e1 = expf(l1 - mx);
            float Z  = c0*e0 + c1*e1;
            p0s[tid] = e0 / Z; p1s[tid] = e1 / Z; flm[tid] = 0;
        } else {
            flm[tid] = 1;   // fully masked row -> uniform softmax -> colsum/N
        }
    }
    __syncthreads();

    // half-Ws: Ws[kk][r], kk in [0,75)
    for (int idx = tid; idx < RT*75; idx += NT) {
        int r = idx / 75, kk = idx - r*75;
        int k = kbase + kk;
        float w;
        if (flm[r]) {
            w = (d_u0[b*N + k] + d_u1[b*N + k]) * (1.0f / (float)N);
        } else {
            w = p0s[r] * __ldg(&d_A0[b*NN + (i0+r)*N + k])
              + p1s[r] * __ldg(&d_A1[b*NN + (i0+r)*N + k]);
        }
        Ws[kk*WRP + r] = w;
    }
    if (tid < 75) Ws[tid*WRP + 15] = 0.f;

    int rg = tid / 80, j = tid % 80;
    bool act = (j < 75);
    float acc[4][2] = {};
    for (int kc = 0; kc < 3; kc++) {
        __syncthreads();
        const float* src = d_Ptmp + bt*NN + (kbase + kc*25)*N;
        for (int idx = tid; idx < 25*N; idx += NT) {
            int kk = idx / N, cc = idx - kk*N;
            PtS[kk*PTS2 + cc] = src[idx];
        }
        __syncthreads();
        if (act) {
            const float* wA = Ws + kc*25*WRP + rg*4;
            const float* pB = PtS + 2*j;
            #pragma unroll 5
            for (int kk = 0; kk < 25; kk++) {
                float4 s  = *(const float4*)(wA + kk*WRP);
                float2 bv = *(const float2*)(pB + kk*PTS2);
                acc[0][0] += s.x*bv.x; acc[0][1] += s.x*bv.y;
                acc[1][0] += s.y*bv.x; acc[1][1] += s.y*bv.y;
                acc[2][0] += s.z*bv.x; acc[2][1] += s.z*bv.y;
                acc[3][0] += s.w*bv.x; acc[3][1] += s.w*bv.y;
            }
        }
    }
    if (act) {
        float* dst = (kh ? d_part1 : d_part0) + bt*NN + i0*N + 2*j;
        #pragma unroll
        for (int u = 0; u < 4; u++) {
            int r = rg*4 + u;
            if (r < RT)
                *(float2*)(dst + r*N) = make_float2(acc[u][0], acc[u][1]);
        }
    }
}

// ==== K2b: out = tanh(part0 + part1) ====
__global__ __launch_bounds__(512) void k2b(float* __restrict__ out) {
    int idx = blockIdx.x*512 + threadIdx.x;
    if (idx < (B*NN)/4) {
        float4 a = ((const float4*)d_part0)[idx];
        float4 c = ((const float4*)d_part1)[idx];
        float4 o;
        o.x = tanhf(a.x + c.x); o.y = tanhf(a.y + c.y);
        o.z = tanhf(a.z + c.z); o.w = tanhf(a.w + c.w);
        ((float4*)out)[idx] = o;
    }
}

// ---------------- launcher ----------------
extern "C" void kernel_launch(void* const* d_in, const int* in_sizes, int n_in,
                              void* d_out, int out_size) {
    const float* H   = (const float*)d_in[0];
    const float* E   = (const float*)d_in[1];
    const float* adj = (const float*)d_in[2];
    const float* WBw = (const float*)d_in[3];
    const float* WBb = (const float*)d_in[4];
    const float* Wfu = (const float*)d_in[5];
    const float* aw  = (const float*)d_in[6];
    float* out = (float*)d_out;

    k1 <<<K1G, NT>>>(H, E, adj, WBw, WBb, Wfu, aw);
    k2a<<<dim3(10, B, 2), NT>>>(out);
    k2b<<<(B*NN/4 + 511)/512, 512>>>(out);
}

// round 11
// speedup vs baseline: 1.9982x; 1.9982x over previous
#include <cuda_runtime.h>

#define BS  2
#define TT  12
#define B   24
#define N   150
#define DIN 64
#define F   128
#define NN  (N*N)     // 22500

#define RT   15       // output rows per GEMM tile
#define RTP  20       // k1 STs row stride
#define GT   10
#define JT   80
#define NT   320
#define NT2  640
#define WFS2 84
#define GEMB 480
#define ABLK 100
#define K1G  (GEMB + ABLK + 1)   // 581
#define KCH  25

// ---------------- scratch ----------------
__device__ float d_Ptmp[B*NN];
__device__ float d_A0[BS*NN];
__device__ float d_A1[BS*NN];
__device__ float d_wg[F];
__device__ float d_cg;
__device__ float d_cnt0[BS*N];
__device__ float d_cnt1[BS*N];
__device__ float d_u0[BS*N];
__device__ float d_u1[BS*N];

// ==== K1: Ptmp GEMM (j-split x2, f-split x2) | A0/A1+counts+colsums | fold ====
__global__ __launch_bounds__(NT) void k1(
        const float* __restrict__ H, const float* __restrict__ E,
        const float* __restrict__ adj,
        const float* __restrict__ WBw, const float* __restrict__ WBb,
        const float* __restrict__ Wfu, const float* __restrict__ aw) {
    __shared__ __align__(16) float sm[5248];   // 21 KB union
    int bid = blockIdx.x, tid = threadIdx.x;

    if (bid < GEMB) {
        // ---- Ptmp GEMM: 15 rows x 80/70 cols, f-split x2 in-block ----
        float* STs = sm;             // 128*20 = 2560
        float* WfS = sm + 2560;      // 2*16*84 = 2688
        int tile2 = bid % 20, bt = bid / 20;
        int tile = tile2 >> 1, jh = tile2 & 1;
        int i0 = tile*RT;
        int W  = jh ? 70 : 80;

        for (int idx = tid; idx < RT*F; idx += NT) {
            int r = idx >> 7, f = idx & 127;
            int row = bt*N + i0 + r;
            float v = (f < DIN) ? H[row*DIN + f] : E[row*DIN + f - DIN];
            STs[f*RTP + r] = v;
        }
        if (tid < F) STs[tid*RTP + 15] = 0.f;
        __syncthreads();

        int kh = tid / 160, t = tid % 160;
        int rg = t / 40, j = t % 40;
        int barid = kh + 1;
        bool act = (j*2 < W);
        float* Wg = WfS + kh*(16*WFS2);

        float acc[4][2] = {};
        for (int fc = 0; fc < 4; fc++) {
            int f0 = kh*64 + fc*16;
            asm volatile("bar.sync %0, %1;" :: "r"(barid), "r"(160) : "memory");
            for (int idx = t; idx < 320; idx += 160) {
                int cc = idx >> 2, q = idx & 3;
                if (cc < W) {
                    float4 w4 = *(const float4*)(Wfu + (jh*80+cc)*F + f0 + q*4);
                    Wg[(q*4+0)*WFS2 + cc] = w4.x;
                    Wg[(q*4+1)*WFS2 + cc] = w4.y;
                    Wg[(q*4+2)*WFS2 + cc] = w4.z;
                    Wg[(q*4+3)*WFS2 + cc] = w4.w;
                }
            }
            asm volatile("bar.sync %0, %1;" :: "r"(barid), "r"(160) : "memory");
            if (act) {
                #pragma unroll
                for (int ff = 0; ff < 16; ff++) {
                    float4 s = *(const float4*)(STs + (f0+ff)*RTP + rg*4);
                    float2 w = *(const float2*)(Wg + ff*WFS2 + 2*j);
                    acc[0][0] += s.x*w.x; acc[0][1] += s.x*w.y;
                    acc[1][0] += s.y*w.x; acc[1][1] += s.y*w.y;
                    acc[2][0] += s.z*w.x; acc[2][1] += s.z*w.y;
                    acc[3][0] += s.w*w.x; acc[3][1] += s.w*w.y;
                }
            }
        }
        __syncthreads();
        float* red = WfS;
        if (kh == 1 && act) {
            #pragma unroll
            for (int u = 0; u < 4; u++) {
                int r = rg*4 + u;
                if (r < RT) {
                    red[r*80 + 2*j]   = acc[u][0];
                    red[r*80 + 2*j+1] = acc[u][1];
                }
            }
        }
        __syncthreads();
        if (kh == 0 && act) {
            #pragma unroll
            for (int u = 0; u < 4; u++) {
                int r = rg*4 + u;
                if (r < RT) {
                    float2 o = make_float2(acc[u][0] + red[r*80 + 2*j],
                                           acc[u][1] + red[r*80 + 2*j+1]);
                    *(float2*)(d_Ptmp + bt*NN + (i0+r)*N + jh*80 + 2*j) = o;
                }
            }
        }
        return;
    }

    if (bid < GEMB + ABLK) {
        // ---- A-half blocks ----
        float* adjS = sm;            // 900
        float* colS = sm + 900;      // 3750
        int ab = bid - GEMB;
        int tile = ab % 25, half = (ab / 25) & 1, b = ab / 50;
        const float* a = adj + b*NN;
        int i0 = tile*6, j0 = half*75;

        for (int idx = tid; idx < 6*N; idx += NT) adjS[idx] = a[i0*N + idx];
        __syncthreads();

        if (tid < 6) {
            float c = 0.f;
            #pragma unroll 5
            for (int j = 0; j < 75; j++)
                c += (adjS[tid*N + j0 + j] > 0.f) ? 1.f : 0.f;
            (half ? d_cnt1 : d_cnt0)[b*N + i0 + tid] = c;
        }

        int g2 = tid / 160, n = tid % 160;
        int r0 = g2*3;
        float a0 = 0.f, a1 = 0.f, a2 = 0.f, us = 0.f;
        for (int c = 0; c < 3; c++) {
            __syncthreads();
            const float* src = a + (j0 + c*25)*N;
            for (int idx = tid; idx < 25*N; idx += NT) colS[idx] = src[idx];
            __syncthreads();
            if (n < N) {
                int jb = j0 + c*25;
                #pragma unroll 5
                for (int jj = 0; jj < 25; jj++) {
                    float v = colS[jj*N + n];
                    us += v;
                    a0 += adjS[(r0+0)*N + jb + jj] * v;
                    a1 += adjS[(r0+1)*N + jb + jj] * v;
                    a2 += adjS[(r0+2)*N + jb + jj] * v;
                }
            }
        }
        if (n < N) {
            float* A = half ? d_A1 : d_A0;
            A[b*NN + (i0+r0+0)*N + n] = a0;
            A[b*NN + (i0+r0+1)*N + n] = a1;
            A[b*NN + (i0+r0+2)*N + n] = a2;
            if (g2 == 0 && tile == 0) (half ? d_u1 : d_u0)[b*N + n] = us;
        }
        return;
    }

    // ---- last block: fold wg, cg ----
    if (tid < F) {
        float acc = 0.f;
        #pragma unroll 8
        for (int h = 0; h < 64; h++)
            acc += WBw[h*F + tid] * (aw[h] + aw[h+64]);
        d_wg[tid] = acc;
    } else if (tid == F) {
        float acc = 0.f;
        for (int h = 0; h < 64; h++) acc += WBb[h] * (aw[h] + aw[h+64]);
        d_cg = acc;
    }
}

// ==== K2: g + softmax + P = tanh(W @ Ptmp); 640 thr, in-block k-split x2 ====
__global__ __launch_bounds__(NT2) void k2(const float* __restrict__ H,
                                          const float* __restrict__ E,
                                          float* __restrict__ out) {
    __shared__ __align__(16) float Ws[N*RTP];      // 12 KB, [k][r]
    __shared__ __align__(16) float PtS[2*KCH*N];   // 30 KB, per-group chunk
    __shared__ float gS[32];
    __shared__ float p0s[RT], p1s[RT];
    __shared__ int   flm[RT];
    int tile = blockIdx.x, bt = blockIdx.y, b = bt / TT;
    int tid  = threadIdx.x;
    int i0   = tile*RT;

    // g for the 32 (30 needed) rows (2*i0 + c) % 150
    if (tid < 256) {
        int c = tid >> 3, seg = tid & 7;
        int row = (2*i0 + c) % N;
        int f0 = seg*16;
        const float* src = (f0 < DIN) ? H + (bt*N+row)*DIN + f0
                                      : E + (bt*N+row)*DIN + f0 - DIN;
        float s = 0.f;
        #pragma unroll
        for (int u = 0; u < 16; u++) s += src[u] * d_wg[f0+u];
        s += __shfl_down_sync(0xffffffffu, s, 4);
        s += __shfl_down_sync(0xffffffffu, s, 2);
        s += __shfl_down_sync(0xffffffffu, s, 1);
        if (seg == 0) gS[c] = s + d_cg;
    }
    __syncthreads();

    if (tid < RT) {
        int i = i0 + tid;
        float v0 = gS[2*tid], v1 = gS[2*tid+1];
        float l0 = v0 > 0.f ? v0 : 0.2f*v0;
        float l1 = v1 > 0.f ? v1 : 0.2f*v1;
        float c0 = d_cnt0[b*N + i], c1 = d_cnt1[b*N + i];
        if (c0 + c1 > 0.f) {
            float mx = fmaxf(l0, l1);
            float e0 = expf(l0 - mx), e1 = expf(l1 - mx);
            float Z  = c0*e0 + c1*e1;
            p0s[tid] = e0 / Z; p1s[tid] = e1 / Z; flm[tid] = 0;
        } else {
            flm[tid] = 1;          // fully masked row -> uniform softmax -> colsum/N
        }
    }
    if (tid < N) Ws[tid*RTP + 15] = 0.f;    // pad row
    __syncthreads();

    // W tile: Ws[k][r] = p0*A0 + p1*A1  (or colsum/N)
    for (int idx = tid; idx < RT*N; idx += NT2) {
        int k = idx % N, r = idx / N;
        float w;
        if (flm[r]) {
            w = (d_u0[b*N + k] + d_u1[b*N + k]) * (1.0f / (float)N);
        } else {
            w = p0s[r] * __ldg(&d_A0[b*NN + (i0+r)*N + k])
              + p1s[r] * __ldg(&d_A1[b*NN + (i0+r)*N + k]);
        }
        Ws[k*RTP + r] = w;
    }
    __syncthreads();

    int kh = tid / NT;          // k-group 0/1
    int t  = tid % NT;
    int j  = t % JT, rg = t / JT;
    int barid = kh + 1;
    float* P = PtS + kh*(KCH*N);

    float acc[4][2] = {};
    for (int kc = 0; kc < 3; kc++) {
        int k0 = kh*75 + kc*KCH;
        asm volatile("bar.sync %0, %1;" :: "r"(barid), "r"(NT) : "memory");
        // bulk-stage 25 rows of Ptmp as float2 (offset k0*N even)
        const float2* src = (const float2*)(d_Ptmp + bt*NN + k0*N);
        float2* dst = (float2*)P;
        for (int idx = t; idx < (KCH*N)/2; idx += NT) dst[idx] = src[idx];
        asm volatile("bar.sync %0, %1;" :: "r"(barid), "r"(NT) : "memory");
        if (j < 75) {
            const float* wA = Ws + k0*RTP + rg*4;
            const float* pB = P + 2*j;
            #pragma unroll 5
            for (int kk = 0; kk < KCH; kk++) {
                float4 s  = *(const float4*)(wA + kk*RTP);
                float2 bv = *(const float2*)(pB + kk*N);
                acc[0][0] += s.x*bv.x; acc[0][1] += s.x*bv.y;
                acc[1][0] += s.y*bv.x; acc[1][1] += s.y*bv.y;
                acc[2][0] += s.z*bv.x; acc[2][1] += s.z*bv.y;
                acc[3][0] += s.w*bv.x; acc[3][1] += s.w*bv.y;
            }
        }
    }

    // cross-group reduce: group 1 dumps into its (dead) staging buffer
    __syncthreads();
    float* red = PtS + KCH*N;
    if (kh == 1 && j < 75) {
        #pragma unroll
        for (int u = 0; u < 4; u++) {
            int r = rg*4 + u;
            if (r < RT) {
                red[r*N + 2*j]     = acc[u][0];
                red[r*N + 2*j + 1] = acc[u][1];
            }
        }
    }
    __syncthreads();
    if (kh == 0 && j < 75) {
        #pragma unroll
        for (int u = 0; u < 4; u++) {
            int r = rg*4 + u;
            if (r < RT) {
                float2 o = make_float2(tanhf(acc[u][0] + red[r*N + 2*j]),
                                       tanhf(acc[u][1] + red[r*N + 2*j + 1]));
                *(float2*)(out + (bt*N + i0 + r)*N + 2*j) = o;
            }
        }
    }
}

// ---------------- launcher ----------------
extern "C" void kernel_launch(void* const* d_in, const int* in_sizes, int n_in,
                              void* d_out, int out_size) {
    const float* H   = (const float*)d_in[0];
    const float* E   = (const float*)d_in[1];
    const float* adj = (const float*)d_in[2];
    const float* WBw = (const float*)d_in[3];
    const float* WBb = (const float*)d_in[4];
    const float* Wfu = (const float*)d_in[5];
    const float* aw  = (const float*)d_in[6];
    float* out = (float*)d_out;

    k1<<<K1G, NT>>>(H, E, adj, WBw, WBb, Wfu, aw);
    k2<<<dim3(GT, B), NT2>>>(H, E, out);
}